// round 15
// baseline (speedup 1.0000x reference)
#include <cuda_runtime.h>
#include <cuda_fp16.h>
#include <math.h>
#include <stdint.h>

#define HID   2048
#define NTOK  8192
#define NH    32
#define HD    64
#define NB    32            /* 8192 / 256 */
#define QKVW  (3*HID)       /* 6144 */

/* ---------------- GEMM tiling (mma.sync fp16, single pass) ----------------- */
#define BM 128
#define BN 128
#define BK 32
#define ST_A 0
#define ST_B 8192
#define STAGE_BYTES 16384           /* 8+8 KB */
#define GEMM_SMEM (2*STAGE_BYTES)   /* 32 KB */

/* ------------------------- scratch (device globals) ------------------------ */
__device__ float g_S  [(size_t)NH * NB * HD * HD];
__device__ float g_KV [(size_t)NH * NB * HD * HD];
__device__ float g_part[(size_t)NTOK * NH];     /* per-(row,head) sumsq */
__device__ float g_rstd[NTOK];
__device__ __half g_qkv_h [(size_t)NTOK * QKVW];
__device__ __half g_hid_h [(size_t)NTOK * HID];
__device__ __half g_hs_h  [(size_t)NTOK * HID];
__device__ __half g_wqkv_h[(size_t)QKVW * HID];
__device__ __half g_wg_h  [(size_t)HID * HID];
__device__ __half g_wo_h  [(size_t)HID * HID];
__device__ __half g_tmp_h [(size_t)NTOK * HID];

/* ------------------------------ PTX helpers -------------------------------- */
__device__ __forceinline__ uint32_t smem_u32(const void* p) {
    uint32_t a;
    asm("{ .reg .u64 t; cvta.to.shared.u64 t, %1; cvt.u32.u64 %0, t; }"
        : "=r"(a) : "l"(p));
    return a;
}
__device__ __forceinline__ void cp16(uint32_t dst, const void* src) {
    asm volatile("cp.async.cg.shared.global [%0], [%1], 16;"
                 :: "r"(dst), "l"(src));
}
#define CP_COMMIT()  asm volatile("cp.async.commit_group;" ::: "memory")
#define CP_WAIT(n)   asm volatile("cp.async.wait_group %0;" :: "n"(n) : "memory")

__device__ __forceinline__ void ldsm4(uint32_t* r, uint32_t addr) {
    asm volatile("ldmatrix.sync.aligned.m8n8.x4.shared.b16 {%0,%1,%2,%3}, [%4];"
                 : "=r"(r[0]), "=r"(r[1]), "=r"(r[2]), "=r"(r[3]) : "r"(addr));
}
__device__ __forceinline__ void ldsm4t(uint32_t* r, uint32_t addr) {
    asm volatile("ldmatrix.sync.aligned.m8n8.x4.trans.shared.b16 {%0,%1,%2,%3}, [%4];"
                 : "=r"(r[0]), "=r"(r[1]), "=r"(r[2]), "=r"(r[3]) : "r"(addr));
}
__device__ __forceinline__ void mma16816(float* d, const uint32_t* a,
                                         const uint32_t* b) {
    asm volatile(
        "mma.sync.aligned.m16n8k16.row.col.f32.f16.f16.f32 "
        "{%0,%1,%2,%3}, {%4,%5,%6,%7}, {%8,%9}, {%0,%1,%2,%3};"
        : "+f"(d[0]), "+f"(d[1]), "+f"(d[2]), "+f"(d[3])
        : "r"(a[0]), "r"(a[1]), "r"(a[2]), "r"(a[3]), "r"(b[0]), "r"(b[1]));
}

__device__ __forceinline__ float head_slope(int h) {
    return exp2f(-0.25f * (float)(h + 1)) * 1.00001f;
}

/* swizzled smem layout: (row, kch) -> 16B slot; rt = number of 8-row tiles */
__device__ __forceinline__ uint32_t smoff(int row, int kch, int rt) {
    return (uint32_t)((kch*rt + (row >> 3))*128 + (((row & 7) ^ (kch & 7)) << 4));
}

/* ---------------------- mma.sync fp16 single-pass GEMM --------------------- */
/* C[m,n] = epi( sum_k A[m,k]*B[n,k] ), A=[M,K] fp16, B=[N,K] fp16.
   EPI 0: C fp32.  EPI 1: silu -> Chalf fp16.
   EPI 2: sigmoid(x)*auxHh[m,n]*rstd[m]*auxW[n] -> Chalf fp16.               */
template<int EPI>
__global__ void __launch_bounds__(256, 2) mma_gemm_kernel(
    const __half* __restrict__ Ah, const __half* __restrict__ Bh,
    int K, int ldC,
    float* __restrict__ C, __half* __restrict__ Chalf,
    const __half* __restrict__ auxHh, const float* __restrict__ auxR,
    const float* __restrict__ auxW)
{
    extern __shared__ char smraw[];
    const uint32_t smu = smem_u32(smraw);
    const int tid  = threadIdx.x;
    const int lane = tid & 31;
    const int wid  = tid >> 5;
    const int m0   = blockIdx.y * BM;
    const int n0   = blockIdx.x * BN;
    const int wm   = (wid >> 2) * 64;
    const int wn   = (wid & 3)  * 32;

    const int r0 = tid >> 2;
    const int kq = tid & 3;

    float acc[4][4][4];
#pragma unroll
    for (int i = 0; i < 4; i++)
#pragma unroll
        for (int j = 0; j < 4; j++)
#pragma unroll
            for (int v = 0; v < 4; v++) acc[i][j][v] = 0.f;

    const int nch = K / BK;

    auto issue = [&](int c, int s) {
        const int kc = c * BK;
        const uint32_t sb = smu + (uint32_t)s * STAGE_BYTES;
#pragma unroll
        for (int i = 0; i < 2; i++) {
            const int r = r0 + 64 * i;
            const uint32_t wo = smoff(r, kq, 16);
            const size_t ga = (size_t)(m0 + r) * K + kc + kq * 8;
            const size_t gb = (size_t)(n0 + r) * K + kc + kq * 8;
            cp16(sb + ST_A + wo, Ah + ga);
            cp16(sb + ST_B + wo, Bh + gb);
        }
        CP_COMMIT();
    };

    issue(0, 0);
    if (nch > 1) issue(1, 1);

    for (int c = 0; c < nch; c++) {
        if (c + 1 < nch) { CP_WAIT(1); } else { CP_WAIT(0); }
        __syncthreads();

        const uint32_t sb = smu + (uint32_t)(c & 1) * STAGE_BYTES;
#pragma unroll
        for (int ks = 0; ks < 2; ks++) {
            uint32_t a[4][4], bh[4][2];
#pragma unroll
            for (int half = 0; half < 2; half++) {
                const int n   = wn + 16*half + ((lane >> 4) << 3) + (lane & 7);
                const int kch = 2*ks + ((lane >> 3) & 1);
                uint32_t t4[4];
                ldsm4(t4, sb + ST_B + smoff(n, kch, 16));
                bh[2*half][0] = t4[0]; bh[2*half][1] = t4[1];
                bh[2*half+1][0] = t4[2]; bh[2*half+1][1] = t4[3];
            }
#pragma unroll
            for (int am = 0; am < 4; am++) {
                const int row = wm + 16*am + (lane & 15);
                const int kch = 2*ks + (lane >> 4);
                ldsm4(a[am], sb + ST_A + smoff(row, kch, 16));
            }
#pragma unroll
            for (int am = 0; am < 4; am++)
#pragma unroll
                for (int bn = 0; bn < 4; bn++)
                    mma16816(acc[am][bn], a[am], bh[bn]);
        }
        __syncthreads();
        if (c + 2 < nch) issue(c + 2, c & 1);
    }

    const int g  = lane >> 2;
    const int t2 = (lane & 3) * 2;
#pragma unroll
    for (int am = 0; am < 4; am++)
#pragma unroll
        for (int bn = 0; bn < 4; bn++) {
            const int n = n0 + wn + 8*bn + t2;
#pragma unroll
            for (int half = 0; half < 2; half++) {
                const int m = m0 + wm + 16*am + g + 8*half;
                const float x0 = acc[am][bn][2*half + 0];
                const float x1 = acc[am][bn][2*half + 1];
                const size_t off = (size_t)m * ldC + n;
                if (EPI == 0) {
                    *(float2*)(C + off) = make_float2(x0, x1);
                } else if (EPI == 1) {
                    float s0 = x0 / (1.f + expf(-x0));
                    float s1 = x1 / (1.f + expf(-x1));
                    *(__half2*)(Chalf + off) =
                        __halves2half2(__float2half_rn(s0), __float2half_rn(s1));
                } else {
                    float2 hv = __half22float2(*(const __half2*)(auxHh + off));
                    float2 wv = *(const float2*)(auxW + n);
                    float rr = auxR[m];
                    float r0v = hv.x * rr * wv.x / (1.f + expf(-x0));
                    float r1v = hv.y * rr * wv.y / (1.f + expf(-x1));
                    *(__half2*)(Chalf + off) =
                        __halves2half2(__float2half_rn(r0v), __float2half_rn(r1v));
                }
            }
        }
}

/* -------------- fused fp32 -> fp16 convert for all four tensors ------------ */
__global__ void __launch_bounds__(256) convall_kernel(
    const float4* __restrict__ s0, __half2* __restrict__ d0, int n0,
    const float4* __restrict__ s1, __half2* __restrict__ d1, int n1,
    const float4* __restrict__ s2, __half2* __restrict__ d2, int n2,
    const float4* __restrict__ s3, __half2* __restrict__ d3, int n3)
{
    int i = blockIdx.x * blockDim.x + threadIdx.x;
    const float4* s; __half2* d; int loc;
    if (i < n0)                { s = s0; d = d0; loc = i; }
    else if (i < n0+n1)        { s = s1; d = d1; loc = i - n0; }
    else if (i < n0+n1+n2)     { s = s2; d = d2; loc = i - n0 - n1; }
    else if (i < n0+n1+n2+n3)  { s = s3; d = d3; loc = i - n0 - n1 - n2; }
    else return;
    float4 v = s[loc];
    d[2*loc]   = __halves2half2(__float2half_rn(v.x), __float2half_rn(v.y));
    d[2*loc+1] = __halves2half2(__float2half_rn(v.z), __float2half_rn(v.w));
}

/* -------- attention A: per-block KV sums  S = (K.*decay)^T @ V  (mma) ------ */
#define KVS_TAB 0
#define KVS_KT  1280
#define KVS_VS  (KVS_KT + 8192)
#define KVS_SMEM (KVS_VS + 8192)      /* 17664 bytes */

__global__ void __launch_bounds__(256) attn_kvsum_kernel(
    const __half* __restrict__ qkvh, float* __restrict__ S)
{
    extern __shared__ char smraw[];
    const uint32_t smu = smem_u32(smraw);
    float* tab = (float*)smraw;

    const int blk = blockIdx.x, h = blockIdx.y;
    const int tid = threadIdx.x;
    const int lane = tid & 31, w = tid >> 5;
    const float slope = head_slope(h);
    for (int i = tid; i < 257; i += 256) tab[i] = expf(-slope * (float)i);

    const int md = (w & 3) * 16;     /* warp's 16 d-rows  */
    const int ne = (w >> 2) * 32;    /* warp's 32 e-cols  */

    float acc[4][4];
#pragma unroll
    for (int bn = 0; bn < 4; bn++)
#pragma unroll
        for (int v = 0; v < 4; v++) acc[bn][v] = 0.f;

    for (int nc = 0; nc < 4; nc++) {
        __syncthreads();
        /* V rows via cp.async (natural [token][e] layout) */
#pragma unroll
        for (int i = 0; i < 2; i++) {
            const int idx = tid + 256*i;
            const int n = idx >> 3, ech = idx & 7;
            cp16(smu + KVS_VS + smoff(n, ech, 8),
                 qkvh + (size_t)(blk*256 + nc*64 + n)*QKVW + h*192 + 128 + ech*8);
        }
        CP_COMMIT();
        /* Kt[d][n] (decayed) scalar staging */
#pragma unroll
        for (int i = 0; i < 16; i++) {
            const int idx = tid + 256*i;
            const int d = idx & 63, n = idx >> 6;
            const int ng = nc*64 + n;
            float kf = __half2float(
                qkvh[(size_t)(blk*256 + ng)*QKVW + h*192 + 64 + d]) * tab[255 - ng];
            *(__half*)(smraw + KVS_KT + smoff(d, n >> 3, 8) + (n & 7)*2) =
                __float2half_rn(kf);
        }
        CP_WAIT(0);
        __syncthreads();

        /* S-tile += Kt-chunk @ V-chunk (k = 64 tokens; B via trans-ldmatrix) */
#pragma unroll
        for (int ks = 0; ks < 4; ks++) {
            uint32_t a[4], b[4][2];
#pragma unroll
            for (int half = 0; half < 2; half++) {
                const int row   = 16*ks + ((lane >> 3) & 1)*8 + (lane & 7);
                const int eslot = (ne >> 3) + 2*half + (lane >> 4);
                uint32_t t4[4];
                ldsm4t(t4, smu + KVS_VS + smoff(row, eslot, 8));
                b[2*half][0] = t4[0]; b[2*half][1] = t4[1];
                b[2*half+1][0] = t4[2]; b[2*half+1][1] = t4[3];
            }
            {
                const int row = md + (lane & 15);
                const int kch = 2*ks + (lane >> 4);
                ldsm4(a, smu + KVS_KT + smoff(row, kch, 8));
            }
#pragma unroll
            for (int bn = 0; bn < 4; bn++)
                mma16816(acc[bn], a, b[bn]);
        }
    }

    const int g = lane >> 2, t2 = (lane & 3)*2;
    float* sp = S + ((size_t)h*NB + blk)*4096;
#pragma unroll
    for (int bn = 0; bn < 4; bn++)
#pragma unroll
        for (int half = 0; half < 2; half++) {
            const int d = md + g + 8*half;
            const int e = ne + 8*bn + t2;
            *(float2*)(sp + d*64 + e) =
                make_float2(acc[bn][2*half+0], acc[bn][2*half+1]);
        }
}

/* ------- attention B: parallel weighted-sum scan (one CTA per (j,h)) ------- */
/* KV[h,j] = bd^j * kv0[h] + sum_{i<j} bd^(j-1-i) * S[h,i]; i-loop unrolled x2
   so ~32 independent loads are in flight (latency hiding).                   */
__global__ void __launch_bounds__(256) attn_scan_kernel(
    const float* __restrict__ S, const float* __restrict__ kv0,
    float* __restrict__ KV)
{
    const int j = blockIdx.x, h = blockIdx.y;
    const int tid = threadIdx.x;
    __shared__ float pw[NB + 1];
    if (tid <= NB) pw[tid] = expf(-head_slope(h) * 256.f * (float)tid);
    __syncthreads();

    float kv[16];
    {
        const float w0 = pw[j];
#pragma unroll
        for (int i = 0; i < 16; i++)
            kv[i] = w0 * kv0[(size_t)h*4096 + tid + i*256];
    }
    int i = 0;
    for (; i + 2 <= j; i += 2) {
        const float wi0 = pw[j - 1 - i];
        const float wi1 = pw[j - 2 - i];
        const float* sp0 = S + ((size_t)h*NB + i)*4096;
        const float* sp1 = sp0 + 4096;
        float v0[16], v1[16];
#pragma unroll
        for (int e = 0; e < 16; e++) { v0[e] = sp0[tid + e*256]; }
#pragma unroll
        for (int e = 0; e < 16; e++) { v1[e] = sp1[tid + e*256]; }
#pragma unroll
        for (int e = 0; e < 16; e++)
            kv[e] += wi0 * v0[e] + wi1 * v1[e];
    }
    if (i < j) {
        const float wi = pw[j - 1 - i];
        const float* sp = S + ((size_t)h*NB + i)*4096;
#pragma unroll
        for (int e = 0; e < 16; e++)
            kv[e] += wi * sp[tid + e*256];
    }
    float* op = KV + ((size_t)h*NB + j)*4096;
#pragma unroll
    for (int e = 0; e < 16; e++) op[tid + e*256] = kv[e];
}

/* --------- attention C: tensor-core tile (inter + masked intra) ------------ */
#define ATN_TAB  0
#define ATN_QS   1280
#define ATN_PS   (ATN_QS + 32768)
#define ATN_KS   (ATN_PS + 32768)
#define ATN_VS   (ATN_KS + 8192)
#define ATN_KVT  (ATN_VS + 8192)
#define ATN_SMEM (ATN_KVT + 8192)     /* 91392 */

__global__ void __launch_bounds__(256) attn_out_kernel(
    const __half* __restrict__ qkvh, const float* __restrict__ KV,
    __half* __restrict__ hidh, float* __restrict__ part)
{
    extern __shared__ char smraw[];
    const uint32_t smu = smem_u32(smraw);
    float* tab = (float*)smraw;

    const int blk = blockIdx.x, h = blockIdx.y;
    const int tid = threadIdx.x;
    const int lane = tid & 31, w = tid >> 5;
    const float slope = head_slope(h);
    for (int i = tid; i < 257; i += 256) tab[i] = expf(-slope * (float)i);

    /* Q tile 256x64 fp16 -> swizzled Qs (cp.async) */
    {
        const int row = tid >> 3, kch = tid & 7;
        const __half* src = qkvh + (size_t)(blk*256)*QKVW + h*192 + kch*8;
#pragma unroll
        for (int i = 0; i < 8; i++) {
            const int r = row + 32*i;
            cp16(smu + ATN_QS + smoff(r, kch, 32), src + (size_t)r*QKVW);
        }
        CP_COMMIT();
    }
    /* KVt[e][d] fp16 from fp32 KV[d][e] */
    {
        const float* kvp = KV + ((size_t)h*NB + blk)*4096;
#pragma unroll
        for (int i = 0; i < 16; i++) {
            const int idx = tid + 256*i;
            const int e = idx & 63, d = idx >> 6;
            *(__half*)(smraw + ATN_KVT + smoff(e, d >> 3, 8) + (d & 7)*2) =
                __float2half_rn(kvp[d*64 + e]);
        }
    }
    CP_WAIT(0);
    __syncthreads();

    const int m0 = w * 32;
    const int g = lane >> 2, t2 = (lane & 3) * 2;

    float acc[2][8][4];
#pragma unroll
    for (int i = 0; i < 2; i++)
#pragma unroll
        for (int j = 0; j < 8; j++)
#pragma unroll
            for (int v = 0; v < 4; v++) acc[i][j][v] = 0.f;

    /* inter: Q @ KVt */
#pragma unroll
    for (int ks = 0; ks < 4; ks++) {
        uint32_t a[2][4], b[8][2];
#pragma unroll
        for (int half = 0; half < 4; half++) {
            const int e   = 16*half + ((lane >> 4) << 3) + (lane & 7);
            const int kch = 2*ks + ((lane >> 3) & 1);
            uint32_t t4[4];
            ldsm4(t4, smu + ATN_KVT + smoff(e, kch, 8));
            b[2*half][0] = t4[0]; b[2*half][1] = t4[1];
            b[2*half+1][0] = t4[2]; b[2*half+1][1] = t4[3];
        }
#pragma unroll
        for (int am = 0; am < 2; am++) {
            const int row = m0 + 16*am + (lane & 15);
            const int kch = 2*ks + (lane >> 4);
            ldsm4(a[am], smu + ATN_QS + smoff(row, kch, 32));
        }
#pragma unroll
        for (int am = 0; am < 2; am++)
#pragma unroll
            for (int bn = 0; bn < 8; bn++)
                mma16816(acc[am][bn], a[am], b[bn]);
    }
#pragma unroll
    for (int am = 0; am < 2; am++)
#pragma unroll
        for (int half = 0; half < 2; half++) {
            const float qd = tab[m0 + 16*am + g + 8*half + 1];
#pragma unroll
            for (int bn = 0; bn < 8; bn++) {
                acc[am][bn][2*half+0] *= qd;
                acc[am][bn][2*half+1] *= qd;
            }
        }

    for (int nc = 0; nc < 4; nc++) {
        __syncthreads();
        /* K rows + V rows via cp.async (both natural layout) */
#pragma unroll
        for (int i = 0; i < 2; i++) {
            const int idx = tid + 256*i;
            const int n = idx >> 3, kch = idx & 7;
            const __half* base =
                qkvh + (size_t)(blk*256 + nc*64 + n)*QKVW + h*192;
            cp16(smu + ATN_KS + smoff(n, kch, 8), base + 64 + kch*8);
            cp16(smu + ATN_VS + smoff(n, kch, 8), base + 128 + kch*8);
        }
        CP_COMMIT();
        CP_WAIT(0);
        __syncthreads();

        if (m0 + 31 >= nc*64) {          /* warp-uniform triangular skip */
            float p[2][8][4];
#pragma unroll
            for (int i = 0; i < 2; i++)
#pragma unroll
                for (int j = 0; j < 8; j++)
#pragma unroll
                    for (int v = 0; v < 4; v++) p[i][j][v] = 0.f;
#pragma unroll
            for (int ks = 0; ks < 4; ks++) {
                uint32_t a[2][4], b[8][2];
#pragma unroll
                for (int half = 0; half < 4; half++) {
                    const int n   = 16*half + ((lane >> 4) << 3) + (lane & 7);
                    const int kch = 2*ks + ((lane >> 3) & 1);
                    uint32_t t4[4];
                    ldsm4(t4, smu + ATN_KS + smoff(n, kch, 8));
                    b[2*half][0] = t4[0]; b[2*half][1] = t4[1];
                    b[2*half+1][0] = t4[2]; b[2*half+1][1] = t4[3];
                }
#pragma unroll
                for (int am = 0; am < 2; am++) {
                    const int row = m0 + 16*am + (lane & 15);
                    const int kch = 2*ks + (lane >> 4);
                    ldsm4(a[am], smu + ATN_QS + smoff(row, kch, 32));
                }
#pragma unroll
                for (int am = 0; am < 2; am++)
#pragma unroll
                    for (int bn = 0; bn < 8; bn++)
                        mma16816(p[am][bn], a[am], b[bn]);
            }
#pragma unroll
            for (int am = 0; am < 2; am++)
#pragma unroll
                for (int half = 0; half < 2; half++) {
                    const int mm = m0 + 16*am + g + 8*half;
#pragma unroll
                    for (int bn = 0; bn < 8; bn++) {
                        const int nnc = 8*bn + t2;
                        const int d0 = mm - (nc*64 + nnc);
                        const int d1 = d0 - 1;
                        const float v0 = (d0 >= 0) ? p[am][bn][2*half+0]*tab[d0] : 0.f;
                        const float v1 = (d1 >= 0) ? p[am][bn][2*half+1]*tab[d1] : 0.f;
                        *(__half2*)(smraw + ATN_PS + smoff(mm, nnc >> 3, 32)
                                    + (nnc & 7)*2) =
                            __halves2half2(__float2half_rn(v0), __float2half_rn(v1));
                    }
                }
            __syncwarp();
            /* out += P @ V   (B fragments via trans-ldmatrix from V rows) */
#pragma unroll
            for (int ks = 0; ks < 4; ks++) {
                uint32_t a[2][4], b[8][2];
#pragma unroll
                for (int half = 0; half < 4; half++) {
                    const int row   = 16*ks + ((lane >> 3) & 1)*8 + (lane & 7);
                    const int eslot = 2*half + (lane >> 4);
                    uint32_t t4[4];
                    ldsm4t(t4, smu + ATN_VS + smoff(row, eslot, 8));
                    b[2*half][0] = t4[0]; b[2*half][1] = t4[1];
                    b[2*half+1][0] = t4[2]; b[2*half+1][1] = t4[3];
                }
#pragma unroll
                for (int am = 0; am < 2; am++) {
                    const int row = m0 + 16*am + (lane & 15);
                    const int kch = 2*ks + (lane >> 4);
                    ldsm4(a[am], smu + ATN_PS + smoff(row, kch, 32));
                }
#pragma unroll
                for (int am = 0; am < 2; am++)
#pragma unroll
                    for (int bn = 0; bn < 8; bn++)
                        mma16816(acc[am][bn], a[am], b[bn]);
            }
        }
    }

    /* epilogue: rmsnorm partial sums + fp16 hid stores */
#pragma unroll
    for (int am = 0; am < 2; am++)
#pragma unroll
        for (int half = 0; half < 2; half++) {
            const int mm = m0 + 16*am + g + 8*half;
            float s = 0.f;
#pragma unroll
            for (int bn = 0; bn < 8; bn++) {
                const float v0 = acc[am][bn][2*half+0];
                const float v1 = acc[am][bn][2*half+1];
                s += v0*v0 + v1*v1;
            }
            s += __shfl_xor_sync(0xffffffffu, s, 1);
            s += __shfl_xor_sync(0xffffffffu, s, 2);
            if ((lane & 3) == 0)
                part[(size_t)(blk*256 + mm)*NH + h] = s;
#pragma unroll
            for (int bn = 0; bn < 8; bn++) {
                const int col = h*64 + 8*bn + t2;
                *(__half2*)(hidh + (size_t)(blk*256 + mm)*HID + col) =
                    __halves2half2(__float2half_rn(acc[am][bn][2*half+0]),
                                   __float2half_rn(acc[am][bn][2*half+1]));
            }
        }
}

/* --------------------- rstd from per-head partial sums ---------------------- */
__global__ void __launch_bounds__(256) rstd_kernel(
    const float* __restrict__ part, float* __restrict__ rstd)
{
    const int row = blockIdx.x * blockDim.x + threadIdx.x;
    if (row >= NTOK) return;
    const float* p = part + (size_t)row * NH;
    float s = 0.f;
#pragma unroll
    for (int i = 0; i < NH; i++) s += p[i];
    rstd[row] = rsqrtf(s * (1.f / HID) + 1e-5f);
}

/* --------------------------------- launch ---------------------------------- */
extern "C" void kernel_launch(void* const* d_in, const int* in_sizes, int n_in,
                              void* d_out, int out_size)
{
    (void)in_sizes; (void)n_in; (void)out_size;
    const float* hs   = (const float*)d_in[0];
    const float* kv0  = (const float*)d_in[1];
    const float* Wqkv = (const float*)d_in[2];
    const float* Wg   = (const float*)d_in[3];
    const float* Wo   = (const float*)d_in[4];
    const float* nw   = (const float*)d_in[5];
    float* out = (float*)d_out;

    float *S, *KV, *part, *rstd;
    __half *qkv_h, *hid_h, *hs_h, *wq_h, *wg_h, *wo_h, *tmp_h;
    cudaGetSymbolAddress((void**)&S,    g_S);
    cudaGetSymbolAddress((void**)&KV,   g_KV);
    cudaGetSymbolAddress((void**)&part, g_part);
    cudaGetSymbolAddress((void**)&rstd, g_rstd);
    cudaGetSymbolAddress((void**)&qkv_h, g_qkv_h);
    cudaGetSymbolAddress((void**)&hid_h, g_hid_h);
    cudaGetSymbolAddress((void**)&hs_h, g_hs_h);
    cudaGetSymbolAddress((void**)&wq_h, g_wqkv_h);
    cudaGetSymbolAddress((void**)&wg_h, g_wg_h);
    cudaGetSymbolAddress((void**)&wo_h, g_wo_h);
    cudaGetSymbolAddress((void**)&tmp_h, g_tmp_h);

    cudaFuncSetAttribute(attn_out_kernel,
                         cudaFuncAttributeMaxDynamicSharedMemorySize, ATN_SMEM);
    cudaFuncSetAttribute(attn_kvsum_kernel,
                         cudaFuncAttributeMaxDynamicSharedMemorySize, KVS_SMEM);
    cudaFuncSetAttribute(mma_gemm_kernel<0>,
                         cudaFuncAttributeMaxDynamicSharedMemorySize, GEMM_SMEM);
    cudaFuncSetAttribute(mma_gemm_kernel<1>,
                         cudaFuncAttributeMaxDynamicSharedMemorySize, GEMM_SMEM);
    cudaFuncSetAttribute(mma_gemm_kernel<2>,
                         cudaFuncAttributeMaxDynamicSharedMemorySize, GEMM_SMEM);

    /* 0. fp16 conversions (fused single launch) */
    const int n0 = NTOK*HID/4, n1 = QKVW*HID/4, n2 = HID*HID/4, n3 = HID*HID/4;
    convall_kernel<<<(n0+n1+n2+n3 + 255)/256, 256>>>(
        (const float4*)hs,   (__half2*)hs_h, n0,
        (const float4*)Wqkv, (__half2*)wq_h, n1,
        (const float4*)Wg,   (__half2*)wg_h, n2,
        (const float4*)Wo,   (__half2*)wo_h, n3);

    /* 1. qkv = silu(hs @ Wqkv^T) -> fp16 */
    mma_gemm_kernel<1><<<dim3(QKVW/BN, NTOK/BM), 256, GEMM_SMEM>>>(
        hs_h, wq_h, HID, QKVW, nullptr, qkv_h, nullptr, nullptr, nullptr);

    /* 2-4. lightning attention (+ fused rmsnorm partials) */
    attn_kvsum_kernel<<<dim3(NB, NH), 256, KVS_SMEM>>>(qkv_h, S);
    attn_scan_kernel<<<dim3(NB, NH), 256>>>(S, kv0, KV);
    attn_out_kernel<<<dim3(NB, NH), 256, ATN_SMEM>>>(qkv_h, KV, hid_h, part);

    /* 5. rstd from partials (1MB read) */
    rstd_kernel<<<NTOK/256, 256>>>(part, rstd);

    /* 6. tmp = sigmoid(hs @ Wg^T) * hid * rstd * nw -> fp16 */
    mma_gemm_kernel<2><<<dim3(HID/BN, NTOK/BM), 256, GEMM_SMEM>>>(
        hs_h, wg_h, HID, HID, nullptr, tmp_h, hid_h, rstd, nw);

    /* 7. out = tmp @ Wo^T */
    mma_gemm_kernel<0><<<dim3(HID/BN, NTOK/BM), 256, GEMM_SMEM>>>(
        tmp_h, wo_h, HID, HID, out, nullptr, nullptr, nullptr, nullptr);
}

// round 16
// speedup vs baseline: 1.0218x; 1.0218x over previous
#include <cuda_runtime.h>
#include <cuda_fp16.h>
#include <math.h>
#include <stdint.h>

#define HID   2048
#define NTOK  8192
#define NH    32
#define HD    64
#define NB    32            /* 8192 / 256 */
#define QKVW  (3*HID)       /* 6144 */

/* ---------------- GEMM tiling (mma.sync fp16, single pass) ----------------- */
#define BM 128
#define BN 128
#define BK 32
#define ST_A 0
#define ST_B 8192
#define STAGE_BYTES 16384           /* 8+8 KB */
#define GEMM_SMEM (2*STAGE_BYTES)   /* 32 KB */

/* ------------------------- scratch (device globals) ------------------------ */
__device__ float g_S  [(size_t)NH * NB * HD * HD];
__device__ float g_KV [(size_t)NH * NB * HD * HD];
__device__ float g_part[(size_t)NTOK * NH];     /* per-(row,head) sumsq */
__device__ float g_rstd[NTOK];
__device__ __half g_qkv_h [(size_t)NTOK * QKVW];
__device__ __half g_hid_h [(size_t)NTOK * HID];
__device__ __half g_hs_h  [(size_t)NTOK * HID];
__device__ __half g_wqkv_h[(size_t)QKVW * HID];
__device__ __half g_wg_h  [(size_t)HID * HID];
__device__ __half g_wo_h  [(size_t)HID * HID];
__device__ __half g_tmp_h [(size_t)NTOK * HID];

/* ------------------------------ PTX helpers -------------------------------- */
__device__ __forceinline__ uint32_t smem_u32(const void* p) {
    uint32_t a;
    asm("{ .reg .u64 t; cvta.to.shared.u64 t, %1; cvt.u32.u64 %0, t; }"
        : "=r"(a) : "l"(p));
    return a;
}
__device__ __forceinline__ void cp16(uint32_t dst, const void* src) {
    asm volatile("cp.async.cg.shared.global [%0], [%1], 16;"
                 :: "r"(dst), "l"(src));
}
#define CP_COMMIT()  asm volatile("cp.async.commit_group;" ::: "memory")
#define CP_WAIT(n)   asm volatile("cp.async.wait_group %0;" :: "n"(n) : "memory")

__device__ __forceinline__ void ldsm4(uint32_t* r, uint32_t addr) {
    asm volatile("ldmatrix.sync.aligned.m8n8.x4.shared.b16 {%0,%1,%2,%3}, [%4];"
                 : "=r"(r[0]), "=r"(r[1]), "=r"(r[2]), "=r"(r[3]) : "r"(addr));
}
__device__ __forceinline__ void ldsm4t(uint32_t* r, uint32_t addr) {
    asm volatile("ldmatrix.sync.aligned.m8n8.x4.trans.shared.b16 {%0,%1,%2,%3}, [%4];"
                 : "=r"(r[0]), "=r"(r[1]), "=r"(r[2]), "=r"(r[3]) : "r"(addr));
}
__device__ __forceinline__ void mma16816(float* d, const uint32_t* a,
                                         const uint32_t* b) {
    asm volatile(
        "mma.sync.aligned.m16n8k16.row.col.f32.f16.f16.f32 "
        "{%0,%1,%2,%3}, {%4,%5,%6,%7}, {%8,%9}, {%0,%1,%2,%3};"
        : "+f"(d[0]), "+f"(d[1]), "+f"(d[2]), "+f"(d[3])
        : "r"(a[0]), "r"(a[1]), "r"(a[2]), "r"(a[3]), "r"(b[0]), "r"(b[1]));
}

__device__ __forceinline__ float head_slope(int h) {
    return exp2f(-0.25f * (float)(h + 1)) * 1.00001f;
}

/* swizzled smem layout: (row, kch) -> 16B slot; rt = number of 8-row tiles */
__device__ __forceinline__ uint32_t smoff(int row, int kch, int rt) {
    return (uint32_t)((kch*rt + (row >> 3))*128 + (((row & 7) ^ (kch & 7)) << 4));
}

/* ---------------------- mma.sync fp16 single-pass GEMM --------------------- */
/* C[m,n] = epi( sum_k A[m,k]*B[n,k] ), A=[M,K] fp16, B=[N,K] fp16.
   EPI 0: C fp32.  EPI 1: silu -> Chalf fp16.
   EPI 2: sigmoid(x)*auxHh[m,n]*rstd[m]*auxW[n] -> Chalf fp16.               */
template<int EPI>
__global__ void __launch_bounds__(256, 2) mma_gemm_kernel(
    const __half* __restrict__ Ah, const __half* __restrict__ Bh,
    int K, int ldC,
    float* __restrict__ C, __half* __restrict__ Chalf,
    const __half* __restrict__ auxHh, const float* __restrict__ auxR,
    const float* __restrict__ auxW)
{
    extern __shared__ char smraw[];
    const uint32_t smu = smem_u32(smraw);
    const int tid  = threadIdx.x;
    const int lane = tid & 31;
    const int wid  = tid >> 5;
    const int m0   = blockIdx.y * BM;
    const int n0   = blockIdx.x * BN;
    const int wm   = (wid >> 2) * 64;
    const int wn   = (wid & 3)  * 32;

    const int r0 = tid >> 2;
    const int kq = tid & 3;

    float acc[4][4][4];
#pragma unroll
    for (int i = 0; i < 4; i++)
#pragma unroll
        for (int j = 0; j < 4; j++)
#pragma unroll
            for (int v = 0; v < 4; v++) acc[i][j][v] = 0.f;

    const int nch = K / BK;

    auto issue = [&](int c, int s) {
        const int kc = c * BK;
        const uint32_t sb = smu + (uint32_t)s * STAGE_BYTES;
#pragma unroll
        for (int i = 0; i < 2; i++) {
            const int r = r0 + 64 * i;
            const uint32_t wo = smoff(r, kq, 16);
            const size_t ga = (size_t)(m0 + r) * K + kc + kq * 8;
            const size_t gb = (size_t)(n0 + r) * K + kc + kq * 8;
            cp16(sb + ST_A + wo, Ah + ga);
            cp16(sb + ST_B + wo, Bh + gb);
        }
        CP_COMMIT();
    };

    issue(0, 0);
    if (nch > 1) issue(1, 1);

    for (int c = 0; c < nch; c++) {
        if (c + 1 < nch) { CP_WAIT(1); } else { CP_WAIT(0); }
        __syncthreads();

        const uint32_t sb = smu + (uint32_t)(c & 1) * STAGE_BYTES;
#pragma unroll
        for (int ks = 0; ks < 2; ks++) {
            uint32_t a[4][4], bh[4][2];
#pragma unroll
            for (int half = 0; half < 2; half++) {
                const int n   = wn + 16*half + ((lane >> 4) << 3) + (lane & 7);
                const int kch = 2*ks + ((lane >> 3) & 1);
                uint32_t t4[4];
                ldsm4(t4, sb + ST_B + smoff(n, kch, 16));
                bh[2*half][0] = t4[0]; bh[2*half][1] = t4[1];
                bh[2*half+1][0] = t4[2]; bh[2*half+1][1] = t4[3];
            }
#pragma unroll
            for (int am = 0; am < 4; am++) {
                const int row = wm + 16*am + (lane & 15);
                const int kch = 2*ks + (lane >> 4);
                ldsm4(a[am], sb + ST_A + smoff(row, kch, 16));
            }
#pragma unroll
            for (int am = 0; am < 4; am++)
#pragma unroll
                for (int bn = 0; bn < 4; bn++)
                    mma16816(acc[am][bn], a[am], bh[bn]);
        }
        __syncthreads();
        if (c + 2 < nch) issue(c + 2, c & 1);
    }

    const int g  = lane >> 2;
    const int t2 = (lane & 3) * 2;
#pragma unroll
    for (int am = 0; am < 4; am++)
#pragma unroll
        for (int bn = 0; bn < 4; bn++) {
            const int n = n0 + wn + 8*bn + t2;
#pragma unroll
            for (int half = 0; half < 2; half++) {
                const int m = m0 + wm + 16*am + g + 8*half;
                const float x0 = acc[am][bn][2*half + 0];
                const float x1 = acc[am][bn][2*half + 1];
                const size_t off = (size_t)m * ldC + n;
                if (EPI == 0) {
                    *(float2*)(C + off) = make_float2(x0, x1);
                } else if (EPI == 1) {
                    float s0 = x0 / (1.f + expf(-x0));
                    float s1 = x1 / (1.f + expf(-x1));
                    *(__half2*)(Chalf + off) =
                        __halves2half2(__float2half_rn(s0), __float2half_rn(s1));
                } else {
                    float2 hv = __half22float2(*(const __half2*)(auxHh + off));
                    float2 wv = *(const float2*)(auxW + n);
                    float rr = auxR[m];
                    float r0v = hv.x * rr * wv.x / (1.f + expf(-x0));
                    float r1v = hv.y * rr * wv.y / (1.f + expf(-x1));
                    *(__half2*)(Chalf + off) =
                        __halves2half2(__float2half_rn(r0v), __float2half_rn(r1v));
                }
            }
        }
}

/* -------------- fused fp32 -> fp16 convert for all four tensors ------------ */
__global__ void __launch_bounds__(256) convall_kernel(
    const float4* __restrict__ s0, __half2* __restrict__ d0, int n0,
    const float4* __restrict__ s1, __half2* __restrict__ d1, int n1,
    const float4* __restrict__ s2, __half2* __restrict__ d2, int n2,
    const float4* __restrict__ s3, __half2* __restrict__ d3, int n3)
{
    int i = blockIdx.x * blockDim.x + threadIdx.x;
    const float4* s; __half2* d; int loc;
    if (i < n0)                { s = s0; d = d0; loc = i; }
    else if (i < n0+n1)        { s = s1; d = d1; loc = i - n0; }
    else if (i < n0+n1+n2)     { s = s2; d = d2; loc = i - n0 - n1; }
    else if (i < n0+n1+n2+n3)  { s = s3; d = d3; loc = i - n0 - n1 - n2; }
    else return;
    float4 v = s[loc];
    d[2*loc]   = __halves2half2(__float2half_rn(v.x), __float2half_rn(v.y));
    d[2*loc+1] = __halves2half2(__float2half_rn(v.z), __float2half_rn(v.w));
}

/* -------- attention A: per-block KV sums  S = (K.*decay)^T @ V  (mma) ------ */
#define KVS_TAB 0
#define KVS_KT  1280
#define KVS_VS  (KVS_KT + 8192)
#define KVS_SMEM (KVS_VS + 8192)      /* 17664 bytes */

__global__ void __launch_bounds__(256) attn_kvsum_kernel(
    const __half* __restrict__ qkvh, float* __restrict__ S)
{
    extern __shared__ char smraw[];
    const uint32_t smu = smem_u32(smraw);
    float* tab = (float*)smraw;

    const int blk = blockIdx.x, h = blockIdx.y;
    const int tid = threadIdx.x;
    const int lane = tid & 31, w = tid >> 5;
    const float slope = head_slope(h);
    for (int i = tid; i < 257; i += 256) tab[i] = expf(-slope * (float)i);

    const int md = (w & 3) * 16;     /* warp's 16 d-rows  */
    const int ne = (w >> 2) * 32;    /* warp's 32 e-cols  */

    float acc[4][4];
#pragma unroll
    for (int bn = 0; bn < 4; bn++)
#pragma unroll
        for (int v = 0; v < 4; v++) acc[bn][v] = 0.f;

    for (int nc = 0; nc < 4; nc++) {
        __syncthreads();
        /* V rows via cp.async (natural [token][e] layout) */
#pragma unroll
        for (int i = 0; i < 2; i++) {
            const int idx = tid + 256*i;
            const int n = idx >> 3, ech = idx & 7;
            cp16(smu + KVS_VS + smoff(n, ech, 8),
                 qkvh + (size_t)(blk*256 + nc*64 + n)*QKVW + h*192 + 128 + ech*8);
        }
        CP_COMMIT();
        /* Kt[d][n] (decayed) scalar staging */
#pragma unroll
        for (int i = 0; i < 16; i++) {
            const int idx = tid + 256*i;
            const int d = idx & 63, n = idx >> 6;
            const int ng = nc*64 + n;
            float kf = __half2float(
                qkvh[(size_t)(blk*256 + ng)*QKVW + h*192 + 64 + d]) * tab[255 - ng];
            *(__half*)(smraw + KVS_KT + smoff(d, n >> 3, 8) + (n & 7)*2) =
                __float2half_rn(kf);
        }
        CP_WAIT(0);
        __syncthreads();

        /* S-tile += Kt-chunk @ V-chunk (k = 64 tokens; B via trans-ldmatrix) */
#pragma unroll
        for (int ks = 0; ks < 4; ks++) {
            uint32_t a[4], b[4][2];
#pragma unroll
            for (int half = 0; half < 2; half++) {
                const int row   = 16*ks + ((lane >> 3) & 1)*8 + (lane & 7);
                const int eslot = (ne >> 3) + 2*half + (lane >> 4);
                uint32_t t4[4];
                ldsm4t(t4, smu + KVS_VS + smoff(row, eslot, 8));
                b[2*half][0] = t4[0]; b[2*half][1] = t4[1];
                b[2*half+1][0] = t4[2]; b[2*half+1][1] = t4[3];
            }
            {
                const int row = md + (lane & 15);
                const int kch = 2*ks + (lane >> 4);
                ldsm4(a, smu + KVS_KT + smoff(row, kch, 8));
            }
#pragma unroll
            for (int bn = 0; bn < 4; bn++)
                mma16816(acc[bn], a, b[bn]);
        }
    }

    const int g = lane >> 2, t2 = (lane & 3)*2;
    float* sp = S + ((size_t)h*NB + blk)*4096;
#pragma unroll
    for (int bn = 0; bn < 4; bn++)
#pragma unroll
        for (int half = 0; half < 2; half++) {
            const int d = md + g + 8*half;
            const int e = ne + 8*bn + t2;
            *(float2*)(sp + d*64 + e) =
                make_float2(acc[bn][2*half+0], acc[bn][2*half+1]);
        }
}

/* --- attention B: serial scan, element-parallel (grid (8,NH), 1 elem/thr) -- */
/* kv = bd*kv + S[j] in original serial order; 4-deep register prefetch ring. */
__global__ void __launch_bounds__(512) attn_scan_kernel(
    const float* __restrict__ S, const float* __restrict__ kv0,
    float* __restrict__ KV)
{
    const int h = blockIdx.y;
    const int e = blockIdx.x * 512 + threadIdx.x;   /* 0..4095 element index */
    const float bd = expf(-head_slope(h) * 256.f);
    const size_t hb = (size_t)h * NB * 4096;

    float kv = kv0[(size_t)h*4096 + e];
    float buf[4];
#pragma unroll
    for (int p = 0; p < 4; p++)
        buf[p] = S[hb + (size_t)p*4096 + e];

    for (int j = 0; j < NB; j++) {
        KV[hb + (size_t)j*4096 + e] = kv;
        kv = bd*kv + buf[j & 3];
        if (j + 4 < NB)
            buf[j & 3] = S[hb + (size_t)(j + 4)*4096 + e];
    }
}

/* --------- attention C: tensor-core tile (inter + masked intra) ------------ */
#define ATN_TAB  0
#define ATN_QS   1280
#define ATN_PS   (ATN_QS + 32768)
#define ATN_KS   (ATN_PS + 32768)
#define ATN_VS   (ATN_KS + 8192)
#define ATN_KVT  (ATN_VS + 8192)
#define ATN_SMEM (ATN_KVT + 8192)     /* 91392 */

__global__ void __launch_bounds__(256) attn_out_kernel(
    const __half* __restrict__ qkvh, const float* __restrict__ KV,
    __half* __restrict__ hidh, float* __restrict__ part)
{
    extern __shared__ char smraw[];
    const uint32_t smu = smem_u32(smraw);
    float* tab = (float*)smraw;

    const int blk = blockIdx.x, h = blockIdx.y;
    const int tid = threadIdx.x;
    const int lane = tid & 31, w = tid >> 5;
    const float slope = head_slope(h);
    for (int i = tid; i < 257; i += 256) tab[i] = expf(-slope * (float)i);

    /* Q tile 256x64 fp16 -> swizzled Qs (cp.async) */
    {
        const int row = tid >> 3, kch = tid & 7;
        const __half* src = qkvh + (size_t)(blk*256)*QKVW + h*192 + kch*8;
#pragma unroll
        for (int i = 0; i < 8; i++) {
            const int r = row + 32*i;
            cp16(smu + ATN_QS + smoff(r, kch, 32), src + (size_t)r*QKVW);
        }
        CP_COMMIT();
    }
    /* KVt[e][d] fp16 from fp32 KV[d][e] */
    {
        const float* kvp = KV + ((size_t)h*NB + blk)*4096;
#pragma unroll
        for (int i = 0; i < 16; i++) {
            const int idx = tid + 256*i;
            const int e = idx & 63, d = idx >> 6;
            *(__half*)(smraw + ATN_KVT + smoff(e, d >> 3, 8) + (d & 7)*2) =
                __float2half_rn(kvp[d*64 + e]);
        }
    }
    CP_WAIT(0);
    __syncthreads();

    const int m0 = w * 32;
    const int g = lane >> 2, t2 = (lane & 3) * 2;

    float acc[2][8][4];
#pragma unroll
    for (int i = 0; i < 2; i++)
#pragma unroll
        for (int j = 0; j < 8; j++)
#pragma unroll
            for (int v = 0; v < 4; v++) acc[i][j][v] = 0.f;

    /* inter: Q @ KVt */
#pragma unroll
    for (int ks = 0; ks < 4; ks++) {
        uint32_t a[2][4], b[8][2];
#pragma unroll
        for (int half = 0; half < 4; half++) {
            const int e   = 16*half + ((lane >> 4) << 3) + (lane & 7);
            const int kch = 2*ks + ((lane >> 3) & 1);
            uint32_t t4[4];
            ldsm4(t4, smu + ATN_KVT + smoff(e, kch, 8));
            b[2*half][0] = t4[0]; b[2*half][1] = t4[1];
            b[2*half+1][0] = t4[2]; b[2*half+1][1] = t4[3];
        }
#pragma unroll
        for (int am = 0; am < 2; am++) {
            const int row = m0 + 16*am + (lane & 15);
            const int kch = 2*ks + (lane >> 4);
            ldsm4(a[am], smu + ATN_QS + smoff(row, kch, 32));
        }
#pragma unroll
        for (int am = 0; am < 2; am++)
#pragma unroll
            for (int bn = 0; bn < 8; bn++)
                mma16816(acc[am][bn], a[am], b[bn]);
    }
#pragma unroll
    for (int am = 0; am < 2; am++)
#pragma unroll
        for (int half = 0; half < 2; half++) {
            const float qd = tab[m0 + 16*am + g + 8*half + 1];
#pragma unroll
            for (int bn = 0; bn < 8; bn++) {
                acc[am][bn][2*half+0] *= qd;
                acc[am][bn][2*half+1] *= qd;
            }
        }

    for (int nc = 0; nc < 4; nc++) {
        __syncthreads();
        /* K rows + V rows via cp.async (both natural layout) */
#pragma unroll
        for (int i = 0; i < 2; i++) {
            const int idx = tid + 256*i;
            const int n = idx >> 3, kch = idx & 7;
            const __half* base =
                qkvh + (size_t)(blk*256 + nc*64 + n)*QKVW + h*192;
            cp16(smu + ATN_KS + smoff(n, kch, 8), base + 64 + kch*8);
            cp16(smu + ATN_VS + smoff(n, kch, 8), base + 128 + kch*8);
        }
        CP_COMMIT();
        CP_WAIT(0);
        __syncthreads();

        if (m0 + 31 >= nc*64) {          /* warp-uniform triangular skip */
            float p[2][8][4];
#pragma unroll
            for (int i = 0; i < 2; i++)
#pragma unroll
                for (int j = 0; j < 8; j++)
#pragma unroll
                    for (int v = 0; v < 4; v++) p[i][j][v] = 0.f;
#pragma unroll
            for (int ks = 0; ks < 4; ks++) {
                uint32_t a[2][4], b[8][2];
#pragma unroll
                for (int half = 0; half < 4; half++) {
                    const int n   = 16*half + ((lane >> 4) << 3) + (lane & 7);
                    const int kch = 2*ks + ((lane >> 3) & 1);
                    uint32_t t4[4];
                    ldsm4(t4, smu + ATN_KS + smoff(n, kch, 8));
                    b[2*half][0] = t4[0]; b[2*half][1] = t4[1];
                    b[2*half+1][0] = t4[2]; b[2*half+1][1] = t4[3];
                }
#pragma unroll
                for (int am = 0; am < 2; am++) {
                    const int row = m0 + 16*am + (lane & 15);
                    const int kch = 2*ks + (lane >> 4);
                    ldsm4(a[am], smu + ATN_QS + smoff(row, kch, 32));
                }
#pragma unroll
                for (int am = 0; am < 2; am++)
#pragma unroll
                    for (int bn = 0; bn < 8; bn++)
                        mma16816(p[am][bn], a[am], b[bn]);
            }
#pragma unroll
            for (int am = 0; am < 2; am++)
#pragma unroll
                for (int half = 0; half < 2; half++) {
                    const int mm = m0 + 16*am + g + 8*half;
#pragma unroll
                    for (int bn = 0; bn < 8; bn++) {
                        const int nnc = 8*bn + t2;
                        const int d0 = mm - (nc*64 + nnc);
                        const int d1 = d0 - 1;
                        const float v0 = (d0 >= 0) ? p[am][bn][2*half+0]*tab[d0] : 0.f;
                        const float v1 = (d1 >= 0) ? p[am][bn][2*half+1]*tab[d1] : 0.f;
                        *(__half2*)(smraw + ATN_PS + smoff(mm, nnc >> 3, 32)
                                    + (nnc & 7)*2) =
                            __halves2half2(__float2half_rn(v0), __float2half_rn(v1));
                    }
                }
            __syncwarp();
            /* out += P @ V   (B fragments via trans-ldmatrix from V rows) */
#pragma unroll
            for (int ks = 0; ks < 4; ks++) {
                uint32_t a[2][4], b[8][2];
#pragma unroll
                for (int half = 0; half < 4; half++) {
                    const int row   = 16*ks + ((lane >> 3) & 1)*8 + (lane & 7);
                    const int eslot = 2*half + (lane >> 4);
                    uint32_t t4[4];
                    ldsm4t(t4, smu + ATN_VS + smoff(row, eslot, 8));
                    b[2*half][0] = t4[0]; b[2*half][1] = t4[1];
                    b[2*half+1][0] = t4[2]; b[2*half+1][1] = t4[3];
                }
#pragma unroll
                for (int am = 0; am < 2; am++) {
                    const int row = m0 + 16*am + (lane & 15);
                    const int kch = 2*ks + (lane >> 4);
                    ldsm4(a[am], smu + ATN_PS + smoff(row, kch, 32));
                }
#pragma unroll
                for (int am = 0; am < 2; am++)
#pragma unroll
                    for (int bn = 0; bn < 8; bn++)
                        mma16816(acc[am][bn], a[am], b[bn]);
            }
        }
    }

    /* epilogue: rmsnorm partial sums + fp16 hid stores */
#pragma unroll
    for (int am = 0; am < 2; am++)
#pragma unroll
        for (int half = 0; half < 2; half++) {
            const int mm = m0 + 16*am + g + 8*half;
            float s = 0.f;
#pragma unroll
            for (int bn = 0; bn < 8; bn++) {
                const float v0 = acc[am][bn][2*half+0];
                const float v1 = acc[am][bn][2*half+1];
                s += v0*v0 + v1*v1;
            }
            s += __shfl_xor_sync(0xffffffffu, s, 1);
            s += __shfl_xor_sync(0xffffffffu, s, 2);
            if ((lane & 3) == 0)
                part[(size_t)(blk*256 + mm)*NH + h] = s;
#pragma unroll
            for (int bn = 0; bn < 8; bn++) {
                const int col = h*64 + 8*bn + t2;
                *(__half2*)(hidh + (size_t)(blk*256 + mm)*HID + col) =
                    __halves2half2(__float2half_rn(acc[am][bn][2*half+0]),
                                   __float2half_rn(acc[am][bn][2*half+1]));
            }
        }
}

/* --------------------- rstd from per-head partial sums ---------------------- */
__global__ void __launch_bounds__(256) rstd_kernel(
    const float* __restrict__ part, float* __restrict__ rstd)
{
    const int row = blockIdx.x * blockDim.x + threadIdx.x;
    if (row >= NTOK) return;
    const float* p = part + (size_t)row * NH;
    float s = 0.f;
#pragma unroll
    for (int i = 0; i < NH; i++) s += p[i];
    rstd[row] = rsqrtf(s * (1.f / HID) + 1e-5f);
}

/* --------------------------------- launch ---------------------------------- */
extern "C" void kernel_launch(void* const* d_in, const int* in_sizes, int n_in,
                              void* d_out, int out_size)
{
    (void)in_sizes; (void)n_in; (void)out_size;
    const float* hs   = (const float*)d_in[0];
    const float* kv0  = (const float*)d_in[1];
    const float* Wqkv = (const float*)d_in[2];
    const float* Wg   = (const float*)d_in[3];
    const float* Wo   = (const float*)d_in[4];
    const float* nw   = (const float*)d_in[5];
    float* out = (float*)d_out;

    float *S, *KV, *part, *rstd;
    __half *qkv_h, *hid_h, *hs_h, *wq_h, *wg_h, *wo_h, *tmp_h;
    cudaGetSymbolAddress((void**)&S,    g_S);
    cudaGetSymbolAddress((void**)&KV,   g_KV);
    cudaGetSymbolAddress((void**)&part, g_part);
    cudaGetSymbolAddress((void**)&rstd, g_rstd);
    cudaGetSymbolAddress((void**)&qkv_h, g_qkv_h);
    cudaGetSymbolAddress((void**)&hid_h, g_hid_h);
    cudaGetSymbolAddress((void**)&hs_h, g_hs_h);
    cudaGetSymbolAddress((void**)&wq_h, g_wqkv_h);
    cudaGetSymbolAddress((void**)&wg_h, g_wg_h);
    cudaGetSymbolAddress((void**)&wo_h, g_wo_h);
    cudaGetSymbolAddress((void**)&tmp_h, g_tmp_h);

    cudaFuncSetAttribute(attn_out_kernel,
                         cudaFuncAttributeMaxDynamicSharedMemorySize, ATN_SMEM);
    cudaFuncSetAttribute(attn_kvsum_kernel,
                         cudaFuncAttributeMaxDynamicSharedMemorySize, KVS_SMEM);
    cudaFuncSetAttribute(mma_gemm_kernel<0>,
                         cudaFuncAttributeMaxDynamicSharedMemorySize, GEMM_SMEM);
    cudaFuncSetAttribute(mma_gemm_kernel<1>,
                         cudaFuncAttributeMaxDynamicSharedMemorySize, GEMM_SMEM);
    cudaFuncSetAttribute(mma_gemm_kernel<2>,
                         cudaFuncAttributeMaxDynamicSharedMemorySize, GEMM_SMEM);

    /* 0. fp16 conversions (fused single launch) */
    const int n0 = NTOK*HID/4, n1 = QKVW*HID/4, n2 = HID*HID/4, n3 = HID*HID/4;
    convall_kernel<<<(n0+n1+n2+n3 + 255)/256, 256>>>(
        (const float4*)hs,   (__half2*)hs_h, n0,
        (const float4*)Wqkv, (__half2*)wq_h, n1,
        (const float4*)Wg,   (__half2*)wg_h, n2,
        (const float4*)Wo,   (__half2*)wo_h, n3);

    /* 1. qkv = silu(hs @ Wqkv^T) -> fp16 */
    mma_gemm_kernel<1><<<dim3(QKVW/BN, NTOK/BM), 256, GEMM_SMEM>>>(
        hs_h, wq_h, HID, QKVW, nullptr, qkv_h, nullptr, nullptr, nullptr);

    /* 2-4. lightning attention (+ fused rmsnorm partials) */
    attn_kvsum_kernel<<<dim3(NB, NH), 256, KVS_SMEM>>>(qkv_h, S);
    attn_scan_kernel<<<dim3(8, NH), 512>>>(S, kv0, KV);
    attn_out_kernel<<<dim3(NB, NH), 256, ATN_SMEM>>>(qkv_h, KV, hid_h, part);

    /* 5. rstd from partials (1MB read) */
    rstd_kernel<<<NTOK/256, 256>>>(part, rstd);

    /* 6. tmp = sigmoid(hs @ Wg^T) * hid * rstd * nw -> fp16 */
    mma_gemm_kernel<2><<<dim3(HID/BN, NTOK/BM), 256, GEMM_SMEM>>>(
        hs_h, wg_h, HID, HID, nullptr, tmp_h, hid_h, rstd, nw);

    /* 7. out = tmp @ Wo^T */
    mma_gemm_kernel<0><<<dim3(HID/BN, NTOK/BM), 256, GEMM_SMEM>>>(
        tmp_h, wo_h, HID, HID, out, nullptr, nullptr, nullptr, nullptr);
}

// round 17
// speedup vs baseline: 1.0412x; 1.0190x over previous
#include <cuda_runtime.h>
#include <cuda_fp16.h>
#include <math.h>
#include <stdint.h>

#define HID   2048
#define NTOK  8192
#define NH    32
#define HD    64
#define NB    32            /* 8192 / 256 */
#define QKVW  (3*HID)       /* 6144 */

/* ---------------- GEMM tiling (mma.sync fp16, single pass) ----------------- */
#define BM 128
#define BN 128
#define BK 32
#define ST_A 0
#define ST_B 8192
#define STAGE_BYTES 16384           /* 8+8 KB */
#define GEMM_SMEM (2*STAGE_BYTES)   /* 32 KB */

/* ------------------------- scratch (device globals) ------------------------ */
__device__ float g_S  [(size_t)NH * NB * HD * HD];
__device__ float g_KV [(size_t)NH * NB * HD * HD];
__device__ float g_part[(size_t)NTOK * NH];     /* per-(row,head) sumsq */
__device__ float g_rstd[NTOK];
__device__ __half g_qkv_h [(size_t)NTOK * QKVW];
__device__ __half g_hid_h [(size_t)NTOK * HID];
__device__ __half g_hs_h  [(size_t)NTOK * HID];
__device__ __half g_wqkv_h[(size_t)QKVW * HID];
__device__ __half g_wg_h  [(size_t)HID * HID];
__device__ __half g_wo_h  [(size_t)HID * HID];
__device__ __half g_tmp_h [(size_t)NTOK * HID];

/* ------------------------------ PTX helpers -------------------------------- */
__device__ __forceinline__ uint32_t smem_u32(const void* p) {
    uint32_t a;
    asm("{ .reg .u64 t; cvta.to.shared.u64 t, %1; cvt.u32.u64 %0, t; }"
        : "=r"(a) : "l"(p));
    return a;
}
__device__ __forceinline__ void cp16(uint32_t dst, const void* src) {
    asm volatile("cp.async.cg.shared.global [%0], [%1], 16;"
                 :: "r"(dst), "l"(src));
}
#define CP_COMMIT()  asm volatile("cp.async.commit_group;" ::: "memory")
#define CP_WAIT(n)   asm volatile("cp.async.wait_group %0;" :: "n"(n) : "memory")

__device__ __forceinline__ void ldsm4(uint32_t* r, uint32_t addr) {
    asm volatile("ldmatrix.sync.aligned.m8n8.x4.shared.b16 {%0,%1,%2,%3}, [%4];"
                 : "=r"(r[0]), "=r"(r[1]), "=r"(r[2]), "=r"(r[3]) : "r"(addr));
}
__device__ __forceinline__ void ldsm4t(uint32_t* r, uint32_t addr) {
    asm volatile("ldmatrix.sync.aligned.m8n8.x4.trans.shared.b16 {%0,%1,%2,%3}, [%4];"
                 : "=r"(r[0]), "=r"(r[1]), "=r"(r[2]), "=r"(r[3]) : "r"(addr));
}
__device__ __forceinline__ void mma16816(float* d, const uint32_t* a,
                                         const uint32_t* b) {
    asm volatile(
        "mma.sync.aligned.m16n8k16.row.col.f32.f16.f16.f32 "
        "{%0,%1,%2,%3}, {%4,%5,%6,%7}, {%8,%9}, {%0,%1,%2,%3};"
        : "+f"(d[0]), "+f"(d[1]), "+f"(d[2]), "+f"(d[3])
        : "r"(a[0]), "r"(a[1]), "r"(a[2]), "r"(a[3]), "r"(b[0]), "r"(b[1]));
}

__device__ __forceinline__ float head_slope(int h) {
    return exp2f(-0.25f * (float)(h + 1)) * 1.00001f;
}

/* multiply packed half2 by per-element fp32 factors, round-to-nearest */
__device__ __forceinline__ uint32_t mulpack(uint32_t x, float da, float db) {
    float2 f = __half22float2(*(__half2*)&x);
    __half2 r = __halves2half2(__float2half_rn(f.x * da), __float2half_rn(f.y * db));
    return *(uint32_t*)&r;
}
/* decayed causal mask + pack to half2 */
__device__ __forceinline__ uint32_t maskpack(float x0, float x1, int mm, int nn,
                                             const float* tab) {
    const int d0 = mm - nn, d1 = d0 - 1;
    const float v0 = (d0 >= 0) ? x0 * tab[d0] : 0.f;
    const float v1 = (d1 >= 0) ? x1 * tab[d1] : 0.f;
    __half2 r = __halves2half2(__float2half_rn(v0), __float2half_rn(v1));
    return *(uint32_t*)&r;
}

/* swizzled smem layout: (row, kch) -> 16B slot; rt = number of 8-row tiles */
__device__ __forceinline__ uint32_t smoff(int row, int kch, int rt) {
    return (uint32_t)((kch*rt + (row >> 3))*128 + (((row & 7) ^ (kch & 7)) << 4));
}

/* ---------------------- mma.sync fp16 single-pass GEMM --------------------- */
/* C[m,n] = epi( sum_k A[m,k]*B[n,k] ), A=[M,K] fp16, B=[N,K] fp16.
   EPI 0: C fp32.  EPI 1: silu -> Chalf fp16.
   EPI 2: sigmoid(x)*auxHh[m,n]*rstd[m]*auxW[n] -> Chalf fp16.               */
template<int EPI>
__global__ void __launch_bounds__(256, 2) mma_gemm_kernel(
    const __half* __restrict__ Ah, const __half* __restrict__ Bh,
    int K, int ldC,
    float* __restrict__ C, __half* __restrict__ Chalf,
    const __half* __restrict__ auxHh, const float* __restrict__ auxR,
    const float* __restrict__ auxW)
{
    extern __shared__ char smraw[];
    const uint32_t smu = smem_u32(smraw);
    const int tid  = threadIdx.x;
    const int lane = tid & 31;
    const int wid  = tid >> 5;
    const int m0   = blockIdx.y * BM;
    const int n0   = blockIdx.x * BN;
    const int wm   = (wid >> 2) * 64;
    const int wn   = (wid & 3)  * 32;

    const int r0 = tid >> 2;
    const int kq = tid & 3;

    float acc[4][4][4];
#pragma unroll
    for (int i = 0; i < 4; i++)
#pragma unroll
        for (int j = 0; j < 4; j++)
#pragma unroll
            for (int v = 0; v < 4; v++) acc[i][j][v] = 0.f;

    const int nch = K / BK;

    auto issue = [&](int c, int s) {
        const int kc = c * BK;
        const uint32_t sb = smu + (uint32_t)s * STAGE_BYTES;
#pragma unroll
        for (int i = 0; i < 2; i++) {
            const int r = r0 + 64 * i;
            const uint32_t wo = smoff(r, kq, 16);
            const size_t ga = (size_t)(m0 + r) * K + kc + kq * 8;
            const size_t gb = (size_t)(n0 + r) * K + kc + kq * 8;
            cp16(sb + ST_A + wo, Ah + ga);
            cp16(sb + ST_B + wo, Bh + gb);
        }
        CP_COMMIT();
    };

    issue(0, 0);
    if (nch > 1) issue(1, 1);

    for (int c = 0; c < nch; c++) {
        if (c + 1 < nch) { CP_WAIT(1); } else { CP_WAIT(0); }
        __syncthreads();

        const uint32_t sb = smu + (uint32_t)(c & 1) * STAGE_BYTES;
#pragma unroll
        for (int ks = 0; ks < 2; ks++) {
            uint32_t a[4][4], bh[4][2];
#pragma unroll
            for (int half = 0; half < 2; half++) {
                const int n   = wn + 16*half + ((lane >> 4) << 3) + (lane & 7);
                const int kch = 2*ks + ((lane >> 3) & 1);
                uint32_t t4[4];
                ldsm4(t4, sb + ST_B + smoff(n, kch, 16));
                bh[2*half][0] = t4[0]; bh[2*half][1] = t4[1];
                bh[2*half+1][0] = t4[2]; bh[2*half+1][1] = t4[3];
            }
#pragma unroll
            for (int am = 0; am < 4; am++) {
                const int row = wm + 16*am + (lane & 15);
                const int kch = 2*ks + (lane >> 4);
                ldsm4(a[am], sb + ST_A + smoff(row, kch, 16));
            }
#pragma unroll
            for (int am = 0; am < 4; am++)
#pragma unroll
                for (int bn = 0; bn < 4; bn++)
                    mma16816(acc[am][bn], a[am], bh[bn]);
        }
        __syncthreads();
        if (c + 2 < nch) issue(c + 2, c & 1);
    }

    const int g  = lane >> 2;
    const int t2 = (lane & 3) * 2;
#pragma unroll
    for (int am = 0; am < 4; am++)
#pragma unroll
        for (int bn = 0; bn < 4; bn++) {
            const int n = n0 + wn + 8*bn + t2;
#pragma unroll
            for (int half = 0; half < 2; half++) {
                const int m = m0 + wm + 16*am + g + 8*half;
                const float x0 = acc[am][bn][2*half + 0];
                const float x1 = acc[am][bn][2*half + 1];
                const size_t off = (size_t)m * ldC + n;
                if (EPI == 0) {
                    *(float2*)(C + off) = make_float2(x0, x1);
                } else if (EPI == 1) {
                    float s0 = x0 / (1.f + expf(-x0));
                    float s1 = x1 / (1.f + expf(-x1));
                    *(__half2*)(Chalf + off) =
                        __halves2half2(__float2half_rn(s0), __float2half_rn(s1));
                } else {
                    float2 hv = __half22float2(*(const __half2*)(auxHh + off));
                    float2 wv = *(const float2*)(auxW + n);
                    float rr = auxR[m];
                    float r0v = hv.x * rr * wv.x / (1.f + expf(-x0));
                    float r1v = hv.y * rr * wv.y / (1.f + expf(-x1));
                    *(__half2*)(Chalf + off) =
                        __halves2half2(__float2half_rn(r0v), __float2half_rn(r1v));
                }
            }
        }
}

/* -------------- fused fp32 -> fp16 convert for all four tensors ------------ */
__global__ void __launch_bounds__(256) convall_kernel(
    const float4* __restrict__ s0, __half2* __restrict__ d0, int n0,
    const float4* __restrict__ s1, __half2* __restrict__ d1, int n1,
    const float4* __restrict__ s2, __half2* __restrict__ d2, int n2,
    const float4* __restrict__ s3, __half2* __restrict__ d3, int n3)
{
    int i = blockIdx.x * blockDim.x + threadIdx.x;
    const float4* s; __half2* d; int loc;
    if (i < n0)                { s = s0; d = d0; loc = i; }
    else if (i < n0+n1)        { s = s1; d = d1; loc = i - n0; }
    else if (i < n0+n1+n2)     { s = s2; d = d2; loc = i - n0 - n1; }
    else if (i < n0+n1+n2+n3)  { s = s3; d = d3; loc = i - n0 - n1 - n2; }
    else return;
    float4 v = s[loc];
    d[2*loc]   = __halves2half2(__float2half_rn(v.x), __float2half_rn(v.y));
    d[2*loc+1] = __halves2half2(__float2half_rn(v.z), __float2half_rn(v.w));
}

/* -------- attention A: per-block KV sums  S = (K.*decay)^T @ V  (mma) ------ */
/* K and V both staged as natural rows via cp.async; Kt A-fragments come from
   trans-ldmatrix with per-token decay applied in registers (same rounding
   chain as scalar staging: fp32(k)*tab -> rn).                               */
#define KVS_TAB 0
#define KVS_KS  1280
#define KVS_VS  (KVS_KS + 8192)
#define KVS_SMEM (KVS_VS + 8192)      /* 17664 bytes */

__global__ void __launch_bounds__(256) attn_kvsum_kernel(
    const __half* __restrict__ qkvh, float* __restrict__ S)
{
    extern __shared__ char smraw[];
    const uint32_t smu = smem_u32(smraw);
    float* tab = (float*)smraw;

    const int blk = blockIdx.x, h = blockIdx.y;
    const int tid = threadIdx.x;
    const int lane = tid & 31, w = tid >> 5;
    const float slope = head_slope(h);
    for (int i = tid; i < 257; i += 256) tab[i] = expf(-slope * (float)i);

    const int md = (w & 3) * 16;     /* warp's 16 d-rows  */
    const int ne = (w >> 2) * 32;    /* warp's 32 e-cols  */
    const int t2 = (lane & 3) * 2;

    float acc[4][4];
#pragma unroll
    for (int bn = 0; bn < 4; bn++)
#pragma unroll
        for (int v = 0; v < 4; v++) acc[bn][v] = 0.f;

    for (int nc = 0; nc < 4; nc++) {
        __syncthreads();
        /* K rows + V rows via cp.async (both natural [token][d/e] layout) */
#pragma unroll
        for (int i = 0; i < 2; i++) {
            const int idx = tid + 256*i;
            const int n = idx >> 3, ch = idx & 7;
            const __half* base =
                qkvh + (size_t)(blk*256 + nc*64 + n)*QKVW + h*192;
            cp16(smu + KVS_KS + smoff(n, ch, 8), base + 64 + ch*8);
            cp16(smu + KVS_VS + smoff(n, ch, 8), base + 128 + ch*8);
        }
        CP_COMMIT();
        CP_WAIT(0);
        __syncthreads();

        /* S-tile += Kt-chunk @ V-chunk (k = 64 tokens) */
#pragma unroll
        for (int ks = 0; ks < 4; ks++) {
            uint32_t a[4], b[4][2];
            /* A: Kt fragments via trans-ldmatrix of K rows + register decay */
            {
                const int row  = 16*ks + ((lane >> 4) << 3) + (lane & 7);
                const int slot = (md >> 3) + ((lane >> 3) & 1);
                ldsm4t(a, smu + KVS_KS + smoff(row, slot, 8));
                const int tk = nc*64 + 16*ks;
                const float d0 = tab[255 - (tk + t2)];
                const float d1 = tab[255 - (tk + t2 + 1)];
                const float d2 = tab[255 - (tk + 8 + t2)];
                const float d3 = tab[255 - (tk + 8 + t2 + 1)];
                a[0] = mulpack(a[0], d0, d1);
                a[1] = mulpack(a[1], d0, d1);
                a[2] = mulpack(a[2], d2, d3);
                a[3] = mulpack(a[3], d2, d3);
            }
            /* B: Vt fragments via trans-ldmatrix (proven path) */
#pragma unroll
            for (int half = 0; half < 2; half++) {
                const int row   = 16*ks + ((lane >> 3) & 1)*8 + (lane & 7);
                const int eslot = (ne >> 3) + 2*half + (lane >> 4);
                uint32_t t4[4];
                ldsm4t(t4, smu + KVS_VS + smoff(row, eslot, 8));
                b[2*half][0] = t4[0]; b[2*half][1] = t4[1];
                b[2*half+1][0] = t4[2]; b[2*half+1][1] = t4[3];
            }
#pragma unroll
            for (int bn = 0; bn < 4; bn++)
                mma16816(acc[bn], a, b[bn]);
        }
    }

    const int g = lane >> 2;
    float* sp = S + ((size_t)h*NB + blk)*4096;
#pragma unroll
    for (int bn = 0; bn < 4; bn++)
#pragma unroll
        for (int half = 0; half < 2; half++) {
            const int d = md + g + 8*half;
            const int e = ne + 8*bn + t2;
            *(float2*)(sp + d*64 + e) =
                make_float2(acc[bn][2*half+0], acc[bn][2*half+1]);
        }
}

/* --- attention B: serial scan, element-parallel (grid (8,NH), 1 elem/thr) -- */
__global__ void __launch_bounds__(512) attn_scan_kernel(
    const float* __restrict__ S, const float* __restrict__ kv0,
    float* __restrict__ KV)
{
    const int h = blockIdx.y;
    const int e = blockIdx.x * 512 + threadIdx.x;
    const float bd = expf(-head_slope(h) * 256.f);
    const size_t hb = (size_t)h * NB * 4096;

    float kv = kv0[(size_t)h*4096 + e];
    float buf[4];
#pragma unroll
    for (int p = 0; p < 4; p++)
        buf[p] = S[hb + (size_t)p*4096 + e];

    for (int j = 0; j < NB; j++) {
        KV[hb + (size_t)j*4096 + e] = kv;
        kv = bd*kv + buf[j & 3];
        if (j + 4 < NB)
            buf[j & 3] = S[hb + (size_t)(j + 4)*4096 + e];
    }
}

/* --------- attention C: tensor-core tile (inter + masked intra) ------------ */
/* P reused register-to-register: QK C-fragments (bn=2ks,2ks+1) are the PV
   A-fragment for k-step ks; decayed causal mask applied during packing.      */
#define ATN_TAB  0
#define ATN_QS   1280
#define ATN_KS   (ATN_QS + 32768)
#define ATN_VS   (ATN_KS + 8192)
#define ATN_KVT  (ATN_VS + 8192)
#define ATN_SMEM (ATN_KVT + 8192)     /* 58624 */

__global__ void __launch_bounds__(256) attn_out_kernel(
    const __half* __restrict__ qkvh, const float* __restrict__ KV,
    __half* __restrict__ hidh, float* __restrict__ part)
{
    extern __shared__ char smraw[];
    const uint32_t smu = smem_u32(smraw);
    float* tab = (float*)smraw;

    const int blk = blockIdx.x, h = blockIdx.y;
    const int tid = threadIdx.x;
    const int lane = tid & 31, w = tid >> 5;
    const float slope = head_slope(h);
    for (int i = tid; i < 257; i += 256) tab[i] = expf(-slope * (float)i);

    /* Q tile 256x64 fp16 -> swizzled Qs (cp.async) */
    {
        const int row = tid >> 3, kch = tid & 7;
        const __half* src = qkvh + (size_t)(blk*256)*QKVW + h*192 + kch*8;
#pragma unroll
        for (int i = 0; i < 8; i++) {
            const int r = row + 32*i;
            cp16(smu + ATN_QS + smoff(r, kch, 32), src + (size_t)r*QKVW);
        }
        CP_COMMIT();
    }
    /* KVt[e][d] fp16 from fp32 KV[d][e] */
    {
        const float* kvp = KV + ((size_t)h*NB + blk)*4096;
#pragma unroll
        for (int i = 0; i < 16; i++) {
            const int idx = tid + 256*i;
            const int e = idx & 63, d = idx >> 6;
            *(__half*)(smraw + ATN_KVT + smoff(e, d >> 3, 8) + (d & 7)*2) =
                __float2half_rn(kvp[d*64 + e]);
        }
    }
    CP_WAIT(0);
    __syncthreads();

    const int m0 = w * 32;
    const int g = lane >> 2, t2 = (lane & 3) * 2;

    float acc[2][8][4];
#pragma unroll
    for (int i = 0; i < 2; i++)
#pragma unroll
        for (int j = 0; j < 8; j++)
#pragma unroll
            for (int v = 0; v < 4; v++) acc[i][j][v] = 0.f;

    /* inter: Q @ KVt */
#pragma unroll
    for (int ks = 0; ks < 4; ks++) {
        uint32_t a[2][4], b[8][2];
#pragma unroll
        for (int half = 0; half < 4; half++) {
            const int e   = 16*half + ((lane >> 4) << 3) + (lane & 7);
            const int kch = 2*ks + ((lane >> 3) & 1);
            uint32_t t4[4];
            ldsm4(t4, smu + ATN_KVT + smoff(e, kch, 8));
            b[2*half][0] = t4[0]; b[2*half][1] = t4[1];
            b[2*half+1][0] = t4[2]; b[2*half+1][1] = t4[3];
        }
#pragma unroll
        for (int am = 0; am < 2; am++) {
            const int row = m0 + 16*am + (lane & 15);
            const int kch = 2*ks + (lane >> 4);
            ldsm4(a[am], smu + ATN_QS + smoff(row, kch, 32));
        }
#pragma unroll
        for (int am = 0; am < 2; am++)
#pragma unroll
            for (int bn = 0; bn < 8; bn++)
                mma16816(acc[am][bn], a[am], b[bn]);
    }
#pragma unroll
    for (int am = 0; am < 2; am++)
#pragma unroll
        for (int half = 0; half < 2; half++) {
            const float qd = tab[m0 + 16*am + g + 8*half + 1];
#pragma unroll
            for (int bn = 0; bn < 8; bn++) {
                acc[am][bn][2*half+0] *= qd;
                acc[am][bn][2*half+1] *= qd;
            }
        }

    for (int nc = 0; nc < 4; nc++) {
        __syncthreads();
        /* K rows + V rows via cp.async (both natural layout) */
#pragma unroll
        for (int i = 0; i < 2; i++) {
            const int idx = tid + 256*i;
            const int n = idx >> 3, kch = idx & 7;
            const __half* base =
                qkvh + (size_t)(blk*256 + nc*64 + n)*QKVW + h*192;
            cp16(smu + ATN_KS + smoff(n, kch, 8), base + 64 + kch*8);
            cp16(smu + ATN_VS + smoff(n, kch, 8), base + 128 + kch*8);
        }
        CP_COMMIT();
        CP_WAIT(0);
        __syncthreads();

        if (m0 + 31 >= nc*64) {          /* warp-uniform triangular skip */
            float p[2][8][4];
#pragma unroll
            for (int i = 0; i < 2; i++)
#pragma unroll
                for (int j = 0; j < 8; j++)
#pragma unroll
                    for (int v = 0; v < 4; v++) p[i][j][v] = 0.f;
            /* P = Q @ K^T */
#pragma unroll
            for (int ks = 0; ks < 4; ks++) {
                uint32_t a[2][4], b[8][2];
#pragma unroll
                for (int half = 0; half < 4; half++) {
                    const int n   = 16*half + ((lane >> 4) << 3) + (lane & 7);
                    const int kch = 2*ks + ((lane >> 3) & 1);
                    uint32_t t4[4];
                    ldsm4(t4, smu + ATN_KS + smoff(n, kch, 8));
                    b[2*half][0] = t4[0]; b[2*half][1] = t4[1];
                    b[2*half+1][0] = t4[2]; b[2*half+1][1] = t4[3];
                }
#pragma unroll
                for (int am = 0; am < 2; am++) {
                    const int row = m0 + 16*am + (lane & 15);
                    const int kch = 2*ks + (lane >> 4);
                    ldsm4(a[am], smu + ATN_QS + smoff(row, kch, 32));
                }
#pragma unroll
                for (int am = 0; am < 2; am++)
#pragma unroll
                    for (int bn = 0; bn < 8; bn++)
                        mma16816(p[am][bn], a[am], b[bn]);
            }
            /* out += P @ V: build A-fragments from P (mask+decay in regs) */
#pragma unroll
            for (int ks = 0; ks < 4; ks++) {
                uint32_t b[8][2];
#pragma unroll
                for (int half = 0; half < 4; half++) {
                    const int row   = 16*ks + ((lane >> 3) & 1)*8 + (lane & 7);
                    const int eslot = 2*half + (lane >> 4);
                    uint32_t t4[4];
                    ldsm4t(t4, smu + ATN_VS + smoff(row, eslot, 8));
                    b[2*half][0] = t4[0]; b[2*half][1] = t4[1];
                    b[2*half+1][0] = t4[2]; b[2*half+1][1] = t4[3];
                }
#pragma unroll
                for (int am = 0; am < 2; am++) {
                    const int bnA  = 2*ks;
                    const int mmlo = m0 + 16*am + g;
                    const int mmhi = mmlo + 8;
                    const int nn0  = nc*64 + 8*bnA + t2;
                    const int nn2  = nn0 + 8;
                    uint32_t a[4];
                    a[0] = maskpack(p[am][bnA][0],   p[am][bnA][1],   mmlo, nn0, tab);
                    a[1] = maskpack(p[am][bnA][2],   p[am][bnA][3],   mmhi, nn0, tab);
                    a[2] = maskpack(p[am][bnA+1][0], p[am][bnA+1][1], mmlo, nn2, tab);
                    a[3] = maskpack(p[am][bnA+1][2], p[am][bnA+1][3], mmhi, nn2, tab);
#pragma unroll
                    for (int bn = 0; bn < 8; bn++)
                        mma16816(acc[am][bn], a, b[bn]);
                }
            }
        }
    }

    /* epilogue: rmsnorm partial sums + fp16 hid stores */
#pragma unroll
    for (int am = 0; am < 2; am++)
#pragma unroll
        for (int half = 0; half < 2; half++) {
            const int mm = m0 + 16*am + g + 8*half;
            float s = 0.f;
#pragma unroll
            for (int bn = 0; bn < 8; bn++) {
                const float v0 = acc[am][bn][2*half+0];
                const float v1 = acc[am][bn][2*half+1];
                s += v0*v0 + v1*v1;
            }
            s += __shfl_xor_sync(0xffffffffu, s, 1);
            s += __shfl_xor_sync(0xffffffffu, s, 2);
            if ((lane & 3) == 0)
                part[(size_t)(blk*256 + mm)*NH + h] = s;
#pragma unroll
            for (int bn = 0; bn < 8; bn++) {
                const int col = h*64 + 8*bn + t2;
                *(__half2*)(hidh + (size_t)(blk*256 + mm)*HID + col) =
                    __halves2half2(__float2half_rn(acc[am][bn][2*half+0]),
                                   __float2half_rn(acc[am][bn][2*half+1]));
            }
        }
}

/* --------------------- rstd from per-head partial sums ---------------------- */
__global__ void __launch_bounds__(256) rstd_kernel(
    const float* __restrict__ part, float* __restrict__ rstd)
{
    const int row = blockIdx.x * blockDim.x + threadIdx.x;
    if (row >= NTOK) return;
    const float* p = part + (size_t)row * NH;
    float s = 0.f;
#pragma unroll
    for (int i = 0; i < NH; i++) s += p[i];
    rstd[row] = rsqrtf(s * (1.f / HID) + 1e-5f);
}

/* --------------------------------- launch ---------------------------------- */
extern "C" void kernel_launch(void* const* d_in, const int* in_sizes, int n_in,
                              void* d_out, int out_size)
{
    (void)in_sizes; (void)n_in; (void)out_size;
    const float* hs   = (const float*)d_in[0];
    const float* kv0  = (const float*)d_in[1];
    const float* Wqkv = (const float*)d_in[2];
    const float* Wg   = (const float*)d_in[3];
    const float* Wo   = (const float*)d_in[4];
    const float* nw   = (const float*)d_in[5];
    float* out = (float*)d_out;

    float *S, *KV, *part, *rstd;
    __half *qkv_h, *hid_h, *hs_h, *wq_h, *wg_h, *wo_h, *tmp_h;
    cudaGetSymbolAddress((void**)&S,    g_S);
    cudaGetSymbolAddress((void**)&KV,   g_KV);
    cudaGetSymbolAddress((void**)&part, g_part);
    cudaGetSymbolAddress((void**)&rstd, g_rstd);
    cudaGetSymbolAddress((void**)&qkv_h, g_qkv_h);
    cudaGetSymbolAddress((void**)&hid_h, g_hid_h);
    cudaGetSymbolAddress((void**)&hs_h, g_hs_h);
    cudaGetSymbolAddress((void**)&wq_h, g_wqkv_h);
    cudaGetSymbolAddress((void**)&wg_h, g_wg_h);
    cudaGetSymbolAddress((void**)&wo_h, g_wo_h);
    cudaGetSymbolAddress((void**)&tmp_h, g_tmp_h);

    cudaFuncSetAttribute(attn_out_kernel,
                         cudaFuncAttributeMaxDynamicSharedMemorySize, ATN_SMEM);
    cudaFuncSetAttribute(attn_kvsum_kernel,
                         cudaFuncAttributeMaxDynamicSharedMemorySize, KVS_SMEM);
    cudaFuncSetAttribute(mma_gemm_kernel<0>,
                         cudaFuncAttributeMaxDynamicSharedMemorySize, GEMM_SMEM);
    cudaFuncSetAttribute(mma_gemm_kernel<1>,
                         cudaFuncAttributeMaxDynamicSharedMemorySize, GEMM_SMEM);
    cudaFuncSetAttribute(mma_gemm_kernel<2>,
                         cudaFuncAttributeMaxDynamicSharedMemorySize, GEMM_SMEM);

    /* 0. fp16 conversions (fused single launch) */
    const int n0 = NTOK*HID/4, n1 = QKVW*HID/4, n2 = HID*HID/4, n3 = HID*HID/4;
    convall_kernel<<<(n0+n1+n2+n3 + 255)/256, 256>>>(
        (const float4*)hs,   (__half2*)hs_h, n0,
        (const float4*)Wqkv, (__half2*)wq_h, n1,
        (const float4*)Wg,   (__half2*)wg_h, n2,
        (const float4*)Wo,   (__half2*)wo_h, n3);

    /* 1. qkv = silu(hs @ Wqkv^T) -> fp16 */
    mma_gemm_kernel<1><<<dim3(QKVW/BN, NTOK/BM), 256, GEMM_SMEM>>>(
        hs_h, wq_h, HID, QKVW, nullptr, qkv_h, nullptr, nullptr, nullptr);

    /* 2-4. lightning attention (+ fused rmsnorm partials) */
    attn_kvsum_kernel<<<dim3(NB, NH), 256, KVS_SMEM>>>(qkv_h, S);
    attn_scan_kernel<<<dim3(8, NH), 512>>>(S, kv0, KV);
    attn_out_kernel<<<dim3(NB, NH), 256, ATN_SMEM>>>(qkv_h, KV, hid_h, part);

    /* 5. rstd from partials (1MB read) */
    rstd_kernel<<<NTOK/256, 256>>>(part, rstd);

    /* 6. tmp = sigmoid(hs @ Wg^T) * hid * rstd * nw -> fp16 */
    mma_gemm_kernel<2><<<dim3(HID/BN, NTOK/BM), 256, GEMM_SMEM>>>(
        hs_h, wg_h, HID, HID, nullptr, tmp_h, hid_h, rstd, nw);

    /* 7. out = tmp @ Wo^T */
    mma_gemm_kernel<0><<<dim3(HID/BN, NTOK/BM), 256, GEMM_SMEM>>>(
        tmp_h, wo_h, HID, HID, out, nullptr, nullptr, nullptr, nullptr);
}